// round 16
// baseline (speedup 1.0000x reference)
#include <cuda_runtime.h>
#include <cuda_bf16.h>
#include <cuda_fp16.h>
#include <cstdint>

#define T_TOK 5888
#define NUMB  46
#define NB    128

typedef __nv_bfloat16 bf16;

// ---------------------------------------------------------------------------
// Scratch (__device__ globals; no allocation allowed)
// ---------------------------------------------------------------------------
__device__ bf16 g_fh[T_TOK * 512];          // feat hi (T, 512)
__device__ bf16 g_fl[T_TOK * 512];          // feat lo
__device__ bf16 g_pwh[3 * 256 * 512];       // [theta|phi|g] weight hi (z,256,512)
__device__ bf16 g_pwl[3 * 256 * 512];       // weight lo
__device__ bf16 g_fwh[512 * 256];           // W_w hi
__device__ bf16 g_fwl[512 * 256];           // W_w lo
__device__ float g_bias[768];               // [theta_b|phi_b|g_b]
__device__ float g_gx[T_TOK * 256];         // gx fp32 (pre-transpose)
__device__ bf16 g_qh[T_TOK * 256];          // x_theta bf16 hi/lo
__device__ bf16 g_ql[T_TOK * 256];
__device__ bf16 g_kh[T_TOK * 256];          // x_phi bf16 hi/lo
__device__ bf16 g_kl[T_TOK * 256];
__device__ __half g_gth[256 * T_TOK];       // g_x^T fp16 hi (256, T)
__device__ __half g_gtl[256 * T_TOK];       // g_x^T fp16 lo
__device__ bf16 g_yh[T_TOK * 256];          // y hi/lo (bf16, for final GEMM)
__device__ bf16 g_yl[T_TOK * 256];
__device__ __half g_pf[34668544];           // P fp16 (T, T)

// ---------------------------------------------------------------------------
// PTX helpers (baseline PTX only)
// ---------------------------------------------------------------------------
__device__ __forceinline__ uint32_t smem_u32(const void* p) {
    uint32_t a;
    asm("{ .reg .u64 t; cvta.to.shared.u64 t, %1; cvt.u32.u64 %0, t; }"
        : "=r"(a) : "l"(p));
    return a;
}
__device__ __forceinline__ void cp16(uint32_t s, const void* g) {
    asm volatile("cp.async.cg.shared.global [%0], [%1], 16;" :: "r"(s), "l"(g) : "memory");
}
__device__ __forceinline__ void cp_commit() {
    asm volatile("cp.async.commit_group;" ::: "memory");
}
template<int N>
__device__ __forceinline__ void cp_wait() {
    asm volatile("cp.async.wait_group %0;" :: "n"(N) : "memory");
}
__device__ __forceinline__ void ldsm4(uint32_t* r, uint32_t addr) {
    asm volatile("ldmatrix.sync.aligned.m8n8.x4.shared.b16 {%0,%1,%2,%3},[%4];"
                 : "=r"(r[0]), "=r"(r[1]), "=r"(r[2]), "=r"(r[3]) : "r"(addr));
}
__device__ __forceinline__ void mma16816(float* c, const uint32_t* a, const uint32_t* b) {
    asm volatile("mma.sync.aligned.m16n8k16.row.col.f32.bf16.bf16.f32 "
                 "{%0,%1,%2,%3},{%4,%5,%6,%7},{%8,%9},{%0,%1,%2,%3};"
                 : "+f"(c[0]), "+f"(c[1]), "+f"(c[2]), "+f"(c[3])
                 : "r"(a[0]), "r"(a[1]), "r"(a[2]), "r"(a[3]),
                   "r"(b[0]), "r"(b[1]));
}
__device__ __forceinline__ void mma16816h(float* c, const uint32_t* a, const uint32_t* b) {
    asm volatile("mma.sync.aligned.m16n8k16.row.col.f32.f16.f16.f32 "
                 "{%0,%1,%2,%3},{%4,%5,%6,%7},{%8,%9},{%0,%1,%2,%3};"
                 : "+f"(c[0]), "+f"(c[1]), "+f"(c[2]), "+f"(c[3])
                 : "r"(a[0]), "r"(a[1]), "r"(a[2]), "r"(a[3]),
                   "r"(b[0]), "r"(b[1]));
}
#define SWZ(x) ((x) ^ (((x) >> 3) & 0x70))

__device__ __forceinline__ void split_bf16(float x, bf16& h, bf16& l) {
    h = __float2bfloat16_rn(x);
    l = __float2bfloat16_rn(x - __bfloat162float(h));
}
__device__ __forceinline__ void split_f16(float x, __half& h, __half& l) {
    h = __float2half_rn(x);
    l = __float2half_rn(x - __half2float(h));
}
__device__ __forceinline__ void store_split2(bf16* H, bf16* L, size_t o,
                                             float v0, float v1) {
    __nv_bfloat162 h2, l2;
    split_bf16(v0, h2.x, l2.x);
    split_bf16(v1, h2.y, l2.y);
    *(__nv_bfloat162*)&H[o] = h2;
    *(__nv_bfloat162*)&L[o] = l2;
}

// ---------------------------------------------------------------------------
// BN(inference)+ReLU+transpose: ori (N,C,46) -> feat hi/lo (T, C) bf16
// ---------------------------------------------------------------------------
__global__ void __launch_bounds__(256)
bn_relu_kernel(const float* __restrict__ ori,
               const float* __restrict__ gamma,
               const float* __restrict__ beta,
               const float* __restrict__ mean,
               const float* __restrict__ var)
{
    __shared__ float s[32][47];
    const int n  = blockIdx.y;
    const int c0 = blockIdx.x * 32;
    const int tid = threadIdx.x;

    for (int i = tid; i < 32 * NUMB; i += 256) {
        int c = i / NUMB;
        int t = i - c * NUMB;
        int cc = c0 + c;
        float inv = gamma[cc] * rsqrtf(var[cc] + 1e-5f);
        float b   = beta[cc] - mean[cc] * inv;
        float v   = ori[(size_t)(n * 512 + cc) * NUMB + t] * inv + b;
        s[c][t] = fmaxf(v, 0.f);
    }
    __syncthreads();
    for (int i = tid; i < 32 * NUMB; i += 256) {
        int t = i >> 5;
        int c = i & 31;
        size_t o = (size_t)(n * NUMB + t) * 512 + c0 + c;
        split_bf16(s[c][t], g_fh[o], g_fl[o]);
    }
}

// ---------------------------------------------------------------------------
// Prep: split weights to bf16 hi/lo, gather biases
// ---------------------------------------------------------------------------
__global__ void __launch_bounds__(256)
prep_weights(const float* __restrict__ tw, const float* __restrict__ pw,
             const float* __restrict__ gw, const float* __restrict__ ww,
             const float* __restrict__ tb, const float* __restrict__ pb,
             const float* __restrict__ gb)
{
    int i = blockIdx.x * 256 + threadIdx.x;
    if (i < 393216) {
        int z = i / 131072;
        int j = i - z * 131072;
        const float* w = (z == 0) ? tw : (z == 1) ? pw : gw;
        split_bf16(w[j], g_pwh[i], g_pwl[i]);
    } else if (i < 524288) {
        int j = i - 393216;
        split_bf16(ww[j], g_fwh[j], g_fwl[j]);
    }
    if (i < 768) {
        float b = (i < 256) ? tb[i] : (i < 512) ? pb[i - 256] : gb[i - 512];
        g_bias[i] = b;
    }
}

// ---------------------------------------------------------------------------
// Transpose gx (T,256) -> Gt fp16 hi/lo (256, T)
// ---------------------------------------------------------------------------
__global__ void __launch_bounds__(256)
transpose_g_kernel()
{
    __shared__ float s[32][33];
    const int r0 = blockIdx.x * 32;
    const int c0 = blockIdx.y * 32;
    const int tx = threadIdx.x & 31;
    const int ty = threadIdx.x >> 5;
#pragma unroll
    for (int i = 0; i < 4; i++) {
        int r = ty + i * 8;
        s[r][tx] = g_gx[(size_t)(r0 + r) * 256 + c0 + tx];
    }
    __syncthreads();
#pragma unroll
    for (int i = 0; i < 4; i++) {
        int c = ty + i * 8;
        size_t o = (size_t)(c0 + c) * T_TOK + r0 + tx;
        split_f16(s[tx][c], g_gth[o], g_gtl[o]);
    }
}

// ---------------------------------------------------------------------------
// HMMA (mma.sync) split NT GEMM: D[M,N] = A@B^T, fp32 accum.
// CTA tile BM x 128, 8 warps (2x4), S=2 cp.async pipeline, SW128 smem,
// OCC CTAs/SM. ONE __syncthreads per chunk (wait+sync at top of iter c orders
// compute(c-1) before the overwrite by load(c+1)).
// TERMS=3: bf16 AhBh + AlBh + AhBl (A 2buf, B 2buf)
// TERMS=2: fp16  A·Bh + A·Bl      (A 1buf, B 2buf)   [AV, BM=32, OCC=3]
// EPI 0: attn (mask, fp32 out)     EPI 1: projections (bias; z-select output)
// EPI 2: AV (emit y hi/lo bf16)    EPI 3: final (bias + residual, fp32 out)
// ---------------------------------------------------------------------------
template<int BM, int S, int EPI, int TERMS, int OCC>
__global__ void __launch_bounds__(256, OCC)
hmma_gemm(const bf16* __restrict__ Ah_, const bf16* __restrict__ Al_,
          const bf16* __restrict__ Bh_, const bf16* __restrict__ Bl_,
          float* __restrict__ C, int ldc, int K,
          const float* __restrict__ bias, const float* __restrict__ ori)
{
    constexpr int MF    = BM / 32;
    constexpr int ASZ   = BM * 128;
    constexpr int ANUM  = (TERMS == 2) ? 1 : 2;
    constexpr int STAGE = ANUM * ASZ + 2 * 16384;

    extern __shared__ char dsm[];
    const uint32_t sb = (smem_u32(dsm) + 1023u) & ~1023u;

    const int tid  = threadIdx.x;
    const int lane = tid & 31;
    const int wid  = tid >> 5;
    const int wm   = wid >> 2;
    const int wn   = wid & 3;
    const int bm   = blockIdx.y * BM;
    const int bn   = blockIdx.x * 128;
    const int z    = (EPI == 1) ? blockIdx.z : 0;

    const bf16* Bh = Bh_;
    const bf16* Bl = Bl_;
    if (EPI == 1) { Bh += (size_t)z * 131072; Bl += (size_t)z * 131072; }

    const size_t ldb = (size_t)K * 2;
    const char* srcAh = (const char*)Ah_ + (size_t)bm * ldb;
    const char* srcAl = (const char*)Al_ + (size_t)bm * ldb;
    const char* srcBh = (const char*)Bh  + (size_t)bn * ldb;
    const char* srcBl = (const char*)Bl  + (size_t)bn * ldb;

    const int NC = K >> 6;

    auto load_stage = [&](int st, int c) {
        uint32_t base = sb + (uint32_t)st * STAGE;
        size_t gof = (size_t)c * 128;
#pragma unroll
        for (int idx = tid; idx < BM * 8; idx += 256) {
            int r = idx >> 3, c16 = (idx & 7) << 4;
            uint32_t sw = SWZ((uint32_t)(r * 128 + c16));
            size_t go = (size_t)r * ldb + c16 + gof;
            cp16(base + sw, srcAh + go);
            if (ANUM == 2) cp16(base + ASZ + sw, srcAl + go);
        }
#pragma unroll
        for (int idx = tid; idx < 128 * 8; idx += 256) {
            int r = idx >> 3, c16 = (idx & 7) << 4;
            uint32_t sw = SWZ((uint32_t)(r * 128 + c16));
            size_t go = (size_t)r * ldb + c16 + gof;
            cp16(base + ANUM * ASZ + sw,         srcBh + go);
            cp16(base + ANUM * ASZ + 16384 + sw, srcBl + go);
        }
        cp_commit();
    };

    uint32_t aBase[MF], aXor[MF];
#pragma unroll
    for (int mf = 0; mf < MF; mf++) {
        int row = wm * (BM / 2) + mf * 16 + (lane & 15);
        aBase[mf] = (uint32_t)(row * 128);
        aXor[mf]  = (uint32_t)((row & 7) << 4);
    }
    const uint32_t akp = (uint32_t)((lane >> 4) * 16);
    uint32_t bBase[2], bXor[2];
#pragma unroll
    for (int np = 0; np < 2; np++) {
        int row = wn * 32 + np * 16 + (lane & 7) + ((lane >> 4) & 1) * 8;
        bBase[np] = (uint32_t)(row * 128);
        bXor[np]  = (uint32_t)((row & 7) << 4);
    }
    const uint32_t bkp = (uint32_t)(((lane >> 3) & 1) * 16);

    float acc[MF][4][4];
#pragma unroll
    for (int i = 0; i < MF; i++)
#pragma unroll
        for (int j = 0; j < 4; j++)
#pragma unroll
            for (int k = 0; k < 4; k++) acc[i][j][k] = 0.f;

    // prologue: stages 0..S-2
#pragma unroll
    for (int s = 0; s < S - 1; s++) load_stage(s, s);

    for (int c = 0; c < NC; c++) {
        int buf = c % S;
        if (S == 2 || c == NC - 1) cp_wait<0>();
        else                       cp_wait<S - 2>();
        __syncthreads();
        if (c + S - 1 < NC) load_stage((c + S - 1) % S, c + S - 1);

        const uint32_t tA  = sb + (uint32_t)buf * STAGE;
        const uint32_t tAl = tA + ASZ;
        const uint32_t tBh = tA + ANUM * ASZ;
        const uint32_t tBl = tBh + 16384;

#pragma unroll
        for (int kk = 0; kk < 4; kk++) {
            uint32_t ah[MF][4], al[MF][4], bh[2][4], bl[2][4];
#pragma unroll
            for (int mf = 0; mf < MF; mf++) {
                uint32_t off = aBase[mf] + (((uint32_t)kk * 32 + akp) ^ aXor[mf]);
                ldsm4(ah[mf], tA + off);
                if (ANUM == 2) ldsm4(al[mf], tAl + off);
            }
#pragma unroll
            for (int np = 0; np < 2; np++) {
                uint32_t off = bBase[np] + (((uint32_t)kk * 32 + bkp) ^ bXor[np]);
                ldsm4(bh[np], tBh + off);
                ldsm4(bl[np], tBl + off);
            }
            if (TERMS == 2) {
#pragma unroll
                for (int mf = 0; mf < MF; mf++)
#pragma unroll
                    for (int nf = 0; nf < 4; nf++)
                        mma16816h(acc[mf][nf], ah[mf], &bh[nf >> 1][(nf & 1) * 2]);
#pragma unroll
                for (int mf = 0; mf < MF; mf++)
#pragma unroll
                    for (int nf = 0; nf < 4; nf++)
                        mma16816h(acc[mf][nf], ah[mf], &bl[nf >> 1][(nf & 1) * 2]);
            } else {
#pragma unroll
                for (int mf = 0; mf < MF; mf++)
#pragma unroll
                    for (int nf = 0; nf < 4; nf++)
                        mma16816(acc[mf][nf], ah[mf], &bh[nf >> 1][(nf & 1) * 2]);
#pragma unroll
                for (int mf = 0; mf < MF; mf++)
#pragma unroll
                    for (int nf = 0; nf < 4; nf++)
                        mma16816(acc[mf][nf], al[mf], &bh[nf >> 1][(nf & 1) * 2]);
#pragma unroll
                for (int mf = 0; mf < MF; mf++)
#pragma unroll
                    for (int nf = 0; nf < 4; nf++)
                        mma16816(acc[mf][nf], ah[mf], &bl[nf >> 1][(nf & 1) * 2]);
            }
        }
        // no end-of-loop barrier (see header comment)
    }

    // ---- epilogue ----
#pragma unroll
    for (int mf = 0; mf < MF; mf++) {
        int rowA = bm + wm * (BM / 2) + mf * 16 + (lane >> 2);
#pragma unroll
        for (int nf = 0; nf < 4; nf++) {
            int col0 = bn + wn * 32 + nf * 8 + ((lane & 3) << 1);
            float v[4] = {acc[mf][nf][0], acc[mf][nf][1],
                          acc[mf][nf][2], acc[mf][nf][3]};
#pragma unroll
            for (int half = 0; half < 2; half++) {
                int row = rowA + half * 8;
                float v0 = v[half * 2], v1 = v[half * 2 + 1];
                if (EPI == 0) {
                    int rb = row / NUMB;
                    if (rb == (col0 + 0) / NUMB) v0 = -1000.0f;
                    if (rb == (col0 + 1) / NUMB) v1 = -1000.0f;
                    *(float2*)&C[(size_t)row * ldc + col0] = make_float2(v0, v1);
                } else if (EPI == 1) {
                    v0 += g_bias[z * 256 + col0];
                    v1 += g_bias[z * 256 + col0 + 1];
                    size_t o = (size_t)row * 256 + col0;
                    if (z == 0)      store_split2(g_qh, g_ql, o, v0, v1);
                    else if (z == 1) store_split2(g_kh, g_kl, o, v0, v1);
                    else             *(float2*)&g_gx[o] = make_float2(v0, v1);
                } else if (EPI == 2) {
                    size_t o = (size_t)row * 256 + col0;
                    store_split2(g_yh, g_yl, o, v0, v1);
                } else {
                    int n = row / NUMB, t = row - n * NUMB;
                    v0 += bias[col0]     + ori[(size_t)(n * 512 + col0) * NUMB + t];
                    v1 += bias[col0 + 1] + ori[(size_t)(n * 512 + col0 + 1) * NUMB + t];
                    *(float2*)&C[(size_t)row * ldc + col0] = make_float2(v0, v1);
                }
            }
        }
    }
}

// ---------------------------------------------------------------------------
// Row softmax in place (float4 vectorized) + emit fp16 P for the AV MMA.
// ---------------------------------------------------------------------------
__global__ void __launch_bounds__(256)
softmax_kernel(float* __restrict__ attn)
{
    const int row = blockIdx.x;
    float4* p4 = (float4*)(attn + (size_t)row * T_TOK);
    uint2*  pf4 = (uint2*)(g_pf + (size_t)row * T_TOK);
    const int tid = threadIdx.x;
    const unsigned FULL = 0xffffffffu;
    __shared__ float red[8];

    float4 v[6];
    float mx = -1e30f;
#pragma unroll
    for (int i = 0; i < 6; i++) {
        int idx = tid + (i << 8);
        if (idx < 1472) {
            v[i] = p4[idx];
            mx = fmaxf(mx, fmaxf(fmaxf(v[i].x, v[i].y), fmaxf(v[i].z, v[i].w)));
        }
    }
#pragma unroll
    for (int o = 16; o; o >>= 1) mx = fmaxf(mx, __shfl_xor_sync(FULL, mx, o));
    if ((tid & 31) == 0) red[tid >> 5] = mx;
    __syncthreads();
    if (tid < 32) {
        float m2 = (tid < 8) ? red[tid] : -1e30f;
#pragma unroll
        for (int o = 4; o; o >>= 1) m2 = fmaxf(m2, __shfl_xor_sync(FULL, m2, o));
        if (tid == 0) red[0] = m2;
    }
    __syncthreads();
    mx = red[0];
    __syncthreads();

    float s = 0.f;
#pragma unroll
    for (int i = 0; i < 6; i++) {
        int idx = tid + (i << 8);
        if (idx < 1472) {
            v[i].x = __expf(v[i].x - mx);
            v[i].y = __expf(v[i].y - mx);
            v[i].z = __expf(v[i].z - mx);
            v[i].w = __expf(v[i].w - mx);
            s += v[i].x + v[i].y + v[i].z + v[i].w;
        }
    }
#pragma unroll
    for (int o = 16; o; o >>= 1) s += __shfl_xor_sync(FULL, s, o);
    if ((tid & 31) == 0) red[tid >> 5] = s;
    __syncthreads();
    if (tid < 32) {
        float s2 = (tid < 8) ? red[tid] : 0.f;
#pragma unroll
        for (int o = 4; o; o >>= 1) s2 += __shfl_xor_sync(FULL, s2, o);
        if (tid == 0) red[0] = s2;
    }
    __syncthreads();
    float inv = 1.f / red[0];
#pragma unroll
    for (int i = 0; i < 6; i++) {
        int idx = tid + (i << 8);
        if (idx < 1472) {
            float4 r;
            r.x = v[i].x * inv; r.y = v[i].y * inv;
            r.z = v[i].z * inv; r.w = v[i].w * inv;
            p4[idx] = r;
            __half2 h0 = __floats2half2_rn(r.x, r.y);
            __half2 h1 = __floats2half2_rn(r.z, r.w);
            uint2 pk;
            pk.x = *(uint32_t*)&h0;
            pk.y = *(uint32_t*)&h1;
            pf4[idx] = pk;
        }
    }
}

// ---------------------------------------------------------------------------
extern "C" void kernel_launch(void* const* d_in, const int* in_sizes, int n_in,
                              void* d_out, int out_size)
{
    const float* ori     = (const float*)d_in[0];
    const float* gamma   = (const float*)d_in[1];
    const float* beta    = (const float*)d_in[2];
    const float* mean    = (const float*)d_in[3];
    const float* var     = (const float*)d_in[4];
    const float* theta_w = (const float*)d_in[5];
    const float* theta_b = (const float*)d_in[6];
    const float* phi_w   = (const float*)d_in[7];
    const float* phi_b   = (const float*)d_in[8];
    const float* g_w     = (const float*)d_in[9];
    const float* g_b     = (const float*)d_in[10];
    const float* W_w     = (const float*)d_in[11];
    const float* W_b     = (const float*)d_in[12];

    float* att_fea = (float*)d_out;                                  // (128,46,512)
    float* fdiv    = (float*)d_out + (size_t)NB * NUMB * 512;        // (5888,5888)

    bf16 *fh, *fl, *pwh, *pwl, *fwh, *fwl;
    bf16 *qh, *ql, *kh, *kl, *yh, *yl;
    __half *gth, *gtl, *pf;
    cudaGetSymbolAddress((void**)&fh,  g_fh);
    cudaGetSymbolAddress((void**)&fl,  g_fl);
    cudaGetSymbolAddress((void**)&pwh, g_pwh);
    cudaGetSymbolAddress((void**)&pwl, g_pwl);
    cudaGetSymbolAddress((void**)&fwh, g_fwh);
    cudaGetSymbolAddress((void**)&fwl, g_fwl);
    cudaGetSymbolAddress((void**)&qh,  g_qh);
    cudaGetSymbolAddress((void**)&ql,  g_ql);
    cudaGetSymbolAddress((void**)&kh,  g_kh);
    cudaGetSymbolAddress((void**)&kl,  g_kl);
    cudaGetSymbolAddress((void**)&gth, g_gth);
    cudaGetSymbolAddress((void**)&gtl, g_gtl);
    cudaGetSymbolAddress((void**)&yh,  g_yh);
    cudaGetSymbolAddress((void**)&yl,  g_yl);
    cudaGetSymbolAddress((void**)&pf,  g_pf);

    // stage = ANUM*BM*128 + 2*16KB
    const int SM3  = 2 * (2 * 8192 + 2 * 16384) + 1024;   // 97 KB (BM=64, TERMS=3)
    const int SMAV = 2 * (1 * 4096 + 2 * 16384) + 1024;   // 74.7 KB (BM=32, TERMS=2)
    cudaFuncSetAttribute(hmma_gemm<64, 2, 0, 3, 2>,
                         cudaFuncAttributeMaxDynamicSharedMemorySize, SM3);
    cudaFuncSetAttribute(hmma_gemm<64, 2, 1, 3, 2>,
                         cudaFuncAttributeMaxDynamicSharedMemorySize, SM3);
    cudaFuncSetAttribute(hmma_gemm<32, 2, 2, 2, 3>,
                         cudaFuncAttributeMaxDynamicSharedMemorySize, SMAV);
    cudaFuncSetAttribute(hmma_gemm<64, 2, 3, 3, 2>,
                         cudaFuncAttributeMaxDynamicSharedMemorySize, SM3);

    // 1) BN + ReLU + transpose -> feat hi/lo (T, 512)
    bn_relu_kernel<<<dim3(16, NB), 256>>>(ori, gamma, beta, mean, var);

    // 2) Split weights / gather biases
    prep_weights<<<2048, 256>>>(theta_w, phi_w, g_w, W_w, theta_b, phi_b, g_b);

    // 3) Projections (HMMA bf16, 3-term): z=0 -> qh/ql, z=1 -> kh/kl, z=2 -> gx
    hmma_gemm<64, 2, 1, 3, 2><<<dim3(2, 92, 3), 256, SM3>>>(
        fh, fl, pwh, pwl, nullptr, 0, 512, nullptr, nullptr);

    // 4) Gt fp16 hi/lo (256, T) transpose of gx
    transpose_g_kernel<<<dim3(184, 8), 256>>>();

    // 5) attn = xt @ xp^T (HMMA bf16, 3-term) + mask -> fdiv logits
    hmma_gemm<64, 2, 0, 3, 2><<<dim3(46, 92), 256, SM3>>>(
        qh, ql, kh, kl, fdiv, T_TOK, 256, nullptr, nullptr);

    // 6) softmax rows in place; emit P fp16
    softmax_kernel<<<T_TOK, 256>>>(fdiv);

    // 7) y = P_f16 @ (Gh + Gl)_f16 (HMMA fp16, 2-term) -> y hi/lo bf16
    //    BM=32, 3 CTAs/SM: 368 CTAs over 444 slots (wave balance fix)
    hmma_gemm<32, 2, 2, 2, 3><<<dim3(2, 184), 256, SMAV>>>(
        (const bf16*)pf, nullptr, (const bf16*)gth, (const bf16*)gtl,
        nullptr, 0, T_TOK, nullptr, nullptr);

    // 8) att_fea = y @ W_w^T + W_b + ori^T (HMMA bf16, 3-term)
    hmma_gemm<64, 2, 3, 3, 2><<<dim3(4, 92), 256, SM3>>>(
        yh, yl, fwh, fwl, att_fea, 512, 256, W_b, ori);
}

// round 17
// speedup vs baseline: 1.0836x; 1.0836x over previous
#include <cuda_runtime.h>
#include <cuda_bf16.h>
#include <cuda_fp16.h>
#include <cstdint>

#define T_TOK 5888
#define NUMB  46
#define NB    128

typedef __nv_bfloat16 bf16;

// ---------------------------------------------------------------------------
// Scratch (__device__ globals; no allocation allowed)
// ---------------------------------------------------------------------------
__device__ bf16 g_fh[T_TOK * 512];          // feat hi (T, 512)
__device__ bf16 g_fl[T_TOK * 512];          // feat lo
__device__ bf16 g_pwh[3 * 256 * 512];       // [theta|phi|g] weight hi (z,256,512)
__device__ bf16 g_pwl[3 * 256 * 512];       // weight lo
__device__ bf16 g_fwh[512 * 256];           // W_w hi
__device__ bf16 g_fwl[512 * 256];           // W_w lo
__device__ float g_bias[768];               // [theta_b|phi_b|g_b]
__device__ float g_gx[T_TOK * 256];         // gx fp32 (pre-transpose)
__device__ bf16 g_qh[T_TOK * 256];          // x_theta bf16 hi/lo
__device__ bf16 g_ql[T_TOK * 256];
__device__ bf16 g_kh[T_TOK * 256];          // x_phi bf16 hi/lo
__device__ bf16 g_kl[T_TOK * 256];
__device__ __half g_gth[256 * T_TOK];       // g_x^T fp16 hi (256, T)
__device__ __half g_gtl[256 * T_TOK];       // g_x^T fp16 lo
__device__ float g_yp[2][T_TOK * 256];      // AV split-K fp32 partials
__device__ bf16 g_yh[T_TOK * 256];          // y hi/lo (bf16, for final GEMM)
__device__ bf16 g_yl[T_TOK * 256];
__device__ __half g_pf[34668544];           // P fp16 (T, T)

// ---------------------------------------------------------------------------
// PTX helpers (baseline PTX only)
// ---------------------------------------------------------------------------
__device__ __forceinline__ uint32_t smem_u32(const void* p) {
    uint32_t a;
    asm("{ .reg .u64 t; cvta.to.shared.u64 t, %1; cvt.u32.u64 %0, t; }"
        : "=r"(a) : "l"(p));
    return a;
}
__device__ __forceinline__ void cp16(uint32_t s, const void* g) {
    asm volatile("cp.async.cg.shared.global [%0], [%1], 16;" :: "r"(s), "l"(g) : "memory");
}
__device__ __forceinline__ void cp_commit() {
    asm volatile("cp.async.commit_group;" ::: "memory");
}
template<int N>
__device__ __forceinline__ void cp_wait() {
    asm volatile("cp.async.wait_group %0;" :: "n"(N) : "memory");
}
__device__ __forceinline__ void ldsm4(uint32_t* r, uint32_t addr) {
    asm volatile("ldmatrix.sync.aligned.m8n8.x4.shared.b16 {%0,%1,%2,%3},[%4];"
                 : "=r"(r[0]), "=r"(r[1]), "=r"(r[2]), "=r"(r[3]) : "r"(addr));
}
__device__ __forceinline__ void mma16816(float* c, const uint32_t* a, const uint32_t* b) {
    asm volatile("mma.sync.aligned.m16n8k16.row.col.f32.bf16.bf16.f32 "
                 "{%0,%1,%2,%3},{%4,%5,%6,%7},{%8,%9},{%0,%1,%2,%3};"
                 : "+f"(c[0]), "+f"(c[1]), "+f"(c[2]), "+f"(c[3])
                 : "r"(a[0]), "r"(a[1]), "r"(a[2]), "r"(a[3]),
                   "r"(b[0]), "r"(b[1]));
}
__device__ __forceinline__ void mma16816h(float* c, const uint32_t* a, const uint32_t* b) {
    asm volatile("mma.sync.aligned.m16n8k16.row.col.f32.f16.f16.f32 "
                 "{%0,%1,%2,%3},{%4,%5,%6,%7},{%8,%9},{%0,%1,%2,%3};"
                 : "+f"(c[0]), "+f"(c[1]), "+f"(c[2]), "+f"(c[3])
                 : "r"(a[0]), "r"(a[1]), "r"(a[2]), "r"(a[3]),
                   "r"(b[0]), "r"(b[1]));
}
#define SWZ(x) ((x) ^ (((x) >> 3) & 0x70))

__device__ __forceinline__ void split_bf16(float x, bf16& h, bf16& l) {
    h = __float2bfloat16_rn(x);
    l = __float2bfloat16_rn(x - __bfloat162float(h));
}
__device__ __forceinline__ void split_f16(float x, __half& h, __half& l) {
    h = __float2half_rn(x);
    l = __float2half_rn(x - __half2float(h));
}
__device__ __forceinline__ void store_split2(bf16* H, bf16* L, size_t o,
                                             float v0, float v1) {
    __nv_bfloat162 h2, l2;
    split_bf16(v0, h2.x, l2.x);
    split_bf16(v1, h2.y, l2.y);
    *(__nv_bfloat162*)&H[o] = h2;
    *(__nv_bfloat162*)&L[o] = l2;
}

// ---------------------------------------------------------------------------
// BN(inference)+ReLU+transpose: ori (N,C,46) -> feat hi/lo (T, C) bf16
// ---------------------------------------------------------------------------
__global__ void __launch_bounds__(256)
bn_relu_kernel(const float* __restrict__ ori,
               const float* __restrict__ gamma,
               const float* __restrict__ beta,
               const float* __restrict__ mean,
               const float* __restrict__ var)
{
    __shared__ float s[32][47];
    const int n  = blockIdx.y;
    const int c0 = blockIdx.x * 32;
    const int tid = threadIdx.x;

    for (int i = tid; i < 32 * NUMB; i += 256) {
        int c = i / NUMB;
        int t = i - c * NUMB;
        int cc = c0 + c;
        float inv = gamma[cc] * rsqrtf(var[cc] + 1e-5f);
        float b   = beta[cc] - mean[cc] * inv;
        float v   = ori[(size_t)(n * 512 + cc) * NUMB + t] * inv + b;
        s[c][t] = fmaxf(v, 0.f);
    }
    __syncthreads();
    for (int i = tid; i < 32 * NUMB; i += 256) {
        int t = i >> 5;
        int c = i & 31;
        size_t o = (size_t)(n * NUMB + t) * 512 + c0 + c;
        split_bf16(s[c][t], g_fh[o], g_fl[o]);
    }
}

// ---------------------------------------------------------------------------
// Prep: split weights to bf16 hi/lo, gather biases
// ---------------------------------------------------------------------------
__global__ void __launch_bounds__(256)
prep_weights(const float* __restrict__ tw, const float* __restrict__ pw,
             const float* __restrict__ gw, const float* __restrict__ ww,
             const float* __restrict__ tb, const float* __restrict__ pb,
             const float* __restrict__ gb)
{
    int i = blockIdx.x * 256 + threadIdx.x;
    if (i < 393216) {
        int z = i / 131072;
        int j = i - z * 131072;
        const float* w = (z == 0) ? tw : (z == 1) ? pw : gw;
        split_bf16(w[j], g_pwh[i], g_pwl[i]);
    } else if (i < 524288) {
        int j = i - 393216;
        split_bf16(ww[j], g_fwh[j], g_fwl[j]);
    }
    if (i < 768) {
        float b = (i < 256) ? tb[i] : (i < 512) ? pb[i - 256] : gb[i - 512];
        g_bias[i] = b;
    }
}

// ---------------------------------------------------------------------------
// Transpose gx (T,256) -> Gt fp16 hi/lo (256, T)
// ---------------------------------------------------------------------------
__global__ void __launch_bounds__(256)
transpose_g_kernel()
{
    __shared__ float s[32][33];
    const int r0 = blockIdx.x * 32;
    const int c0 = blockIdx.y * 32;
    const int tx = threadIdx.x & 31;
    const int ty = threadIdx.x >> 5;
#pragma unroll
    for (int i = 0; i < 4; i++) {
        int r = ty + i * 8;
        s[r][tx] = g_gx[(size_t)(r0 + r) * 256 + c0 + tx];
    }
    __syncthreads();
#pragma unroll
    for (int i = 0; i < 4; i++) {
        int c = ty + i * 8;
        size_t o = (size_t)(c0 + c) * T_TOK + r0 + tx;
        split_f16(s[tx][c], g_gth[o], g_gtl[o]);
    }
}

// ---------------------------------------------------------------------------
// Reduce AV split-K partials: yh/yl = split(p0 + p1), float4 per thread
// ---------------------------------------------------------------------------
__global__ void __launch_bounds__(256)
reduce_y_kernel()
{
    int i = blockIdx.x * 256 + threadIdx.x;   // float4 index, T*256/4 total
    float4 a = ((const float4*)g_yp[0])[i];
    float4 b = ((const float4*)g_yp[1])[i];
    float4 r;
    r.x = a.x + b.x; r.y = a.y + b.y; r.z = a.z + b.z; r.w = a.w + b.w;
    size_t o = (size_t)i * 4;
    store_split2(g_yh, g_yl, o,     r.x, r.y);
    store_split2(g_yh, g_yl, o + 2, r.z, r.w);
}

// ---------------------------------------------------------------------------
// HMMA (mma.sync) split NT GEMM: D[M,N] = A@B^T, fp32 accum.
// CTA tile BM=64 x 128, 8 warps (2x4), S=2 cp.async pipeline, SW128 smem,
// 2 CTAs/SM. ONE __syncthreads per chunk (wait+sync at top of iter c orders
// compute(c-1) before the overwrite by load(c+1)).
// ld = full row length in elements; K = elements processed by this CTA.
// TERMS=3: bf16 AhBh + AlBh + AhBl (A 2buf, B 2buf)
// TERMS=2: fp16  A·Bh + A·Bl      (A 1buf, B 2buf)   [AV split-K]
// EPI 0: attn (mask, fp32 out)     EPI 1: projections (bias; z-select output)
// EPI 2: AV split-K (fp32 partial to g_yp[z], k0 = z*K)
// EPI 3: final (bias + residual, fp32 out)
// ---------------------------------------------------------------------------
template<int BM, int S, int EPI, int TERMS>
__global__ void __launch_bounds__(256, 2)
hmma_gemm(const bf16* __restrict__ Ah_, const bf16* __restrict__ Al_,
          const bf16* __restrict__ Bh_, const bf16* __restrict__ Bl_,
          float* __restrict__ C, int ldc, int ld, int K,
          const float* __restrict__ bias, const float* __restrict__ ori)
{
    constexpr int MF    = BM / 32;
    constexpr int ASZ   = BM * 128;
    constexpr int ANUM  = (TERMS == 2) ? 1 : 2;
    constexpr int STAGE = ANUM * ASZ + 2 * 16384;

    extern __shared__ char dsm[];
    const uint32_t sb = (smem_u32(dsm) + 1023u) & ~1023u;

    const int tid  = threadIdx.x;
    const int lane = tid & 31;
    const int wid  = tid >> 5;
    const int wm   = wid >> 2;
    const int wn   = wid & 3;
    const int bm   = blockIdx.y * BM;
    const int bn   = blockIdx.x * 128;
    const int z    = (EPI == 1 || EPI == 2) ? blockIdx.z : 0;

    const bf16* Bh = Bh_;
    const bf16* Bl = Bl_;
    if (EPI == 1) { Bh += (size_t)z * 131072; Bl += (size_t)z * 131072; }

    const size_t k0b = (EPI == 2) ? (size_t)z * K * 2 : 0;   // byte offset
    float* Cp = C;
    if (EPI == 2) Cp += (size_t)z * T_TOK * 256;

    const size_t ldb = (size_t)ld * 2;
    const char* srcAh = (const char*)Ah_ + (size_t)bm * ldb + k0b;
    const char* srcAl = (const char*)Al_ + (size_t)bm * ldb + k0b;
    const char* srcBh = (const char*)Bh  + (size_t)bn * ldb + k0b;
    const char* srcBl = (const char*)Bl  + (size_t)bn * ldb + k0b;

    const int NC = K >> 6;

    auto load_stage = [&](int st, int c) {
        uint32_t base = sb + (uint32_t)st * STAGE;
        size_t gof = (size_t)c * 128;
#pragma unroll
        for (int idx = tid; idx < BM * 8; idx += 256) {
            int r = idx >> 3, c16 = (idx & 7) << 4;
            uint32_t sw = SWZ((uint32_t)(r * 128 + c16));
            size_t go = (size_t)r * ldb + c16 + gof;
            cp16(base + sw, srcAh + go);
            if (ANUM == 2) cp16(base + ASZ + sw, srcAl + go);
        }
#pragma unroll
        for (int idx = tid; idx < 128 * 8; idx += 256) {
            int r = idx >> 3, c16 = (idx & 7) << 4;
            uint32_t sw = SWZ((uint32_t)(r * 128 + c16));
            size_t go = (size_t)r * ldb + c16 + gof;
            cp16(base + ANUM * ASZ + sw,         srcBh + go);
            cp16(base + ANUM * ASZ + 16384 + sw, srcBl + go);
        }
        cp_commit();
    };

    uint32_t aBase[MF], aXor[MF];
#pragma unroll
    for (int mf = 0; mf < MF; mf++) {
        int row = wm * (BM / 2) + mf * 16 + (lane & 15);
        aBase[mf] = (uint32_t)(row * 128);
        aXor[mf]  = (uint32_t)((row & 7) << 4);
    }
    const uint32_t akp = (uint32_t)((lane >> 4) * 16);
    uint32_t bBase[2], bXor[2];
#pragma unroll
    for (int np = 0; np < 2; np++) {
        int row = wn * 32 + np * 16 + (lane & 7) + ((lane >> 4) & 1) * 8;
        bBase[np] = (uint32_t)(row * 128);
        bXor[np]  = (uint32_t)((row & 7) << 4);
    }
    const uint32_t bkp = (uint32_t)(((lane >> 3) & 1) * 16);

    float acc[MF][4][4];
#pragma unroll
    for (int i = 0; i < MF; i++)
#pragma unroll
        for (int j = 0; j < 4; j++)
#pragma unroll
            for (int k = 0; k < 4; k++) acc[i][j][k] = 0.f;

    // prologue: stages 0..S-2
#pragma unroll
    for (int s = 0; s < S - 1; s++) load_stage(s, s);

    for (int c = 0; c < NC; c++) {
        int buf = c % S;
        if (S == 2 || c == NC - 1) cp_wait<0>();
        else                       cp_wait<S - 2>();
        __syncthreads();
        if (c + S - 1 < NC) load_stage((c + S - 1) % S, c + S - 1);

        const uint32_t tA  = sb + (uint32_t)buf * STAGE;
        const uint32_t tAl = tA + ASZ;
        const uint32_t tBh = tA + ANUM * ASZ;
        const uint32_t tBl = tBh + 16384;

#pragma unroll
        for (int kk = 0; kk < 4; kk++) {
            uint32_t ah[MF][4], al[MF][4], bh[2][4], bl[2][4];
#pragma unroll
            for (int mf = 0; mf < MF; mf++) {
                uint32_t off = aBase[mf] + (((uint32_t)kk * 32 + akp) ^ aXor[mf]);
                ldsm4(ah[mf], tA + off);
                if (ANUM == 2) ldsm4(al[mf], tAl + off);
            }
#pragma unroll
            for (int np = 0; np < 2; np++) {
                uint32_t off = bBase[np] + (((uint32_t)kk * 32 + bkp) ^ bXor[np]);
                ldsm4(bh[np], tBh + off);
                ldsm4(bl[np], tBl + off);
            }
            if (TERMS == 2) {
#pragma unroll
                for (int mf = 0; mf < MF; mf++)
#pragma unroll
                    for (int nf = 0; nf < 4; nf++)
                        mma16816h(acc[mf][nf], ah[mf], &bh[nf >> 1][(nf & 1) * 2]);
#pragma unroll
                for (int mf = 0; mf < MF; mf++)
#pragma unroll
                    for (int nf = 0; nf < 4; nf++)
                        mma16816h(acc[mf][nf], ah[mf], &bl[nf >> 1][(nf & 1) * 2]);
            } else {
#pragma unroll
                for (int mf = 0; mf < MF; mf++)
#pragma unroll
                    for (int nf = 0; nf < 4; nf++)
                        mma16816(acc[mf][nf], ah[mf], &bh[nf >> 1][(nf & 1) * 2]);
#pragma unroll
                for (int mf = 0; mf < MF; mf++)
#pragma unroll
                    for (int nf = 0; nf < 4; nf++)
                        mma16816(acc[mf][nf], al[mf], &bh[nf >> 1][(nf & 1) * 2]);
#pragma unroll
                for (int mf = 0; mf < MF; mf++)
#pragma unroll
                    for (int nf = 0; nf < 4; nf++)
                        mma16816(acc[mf][nf], ah[mf], &bl[nf >> 1][(nf & 1) * 2]);
            }
        }
        // no end-of-loop barrier (see header comment)
    }

    // ---- epilogue ----
#pragma unroll
    for (int mf = 0; mf < MF; mf++) {
        int rowA = bm + wm * (BM / 2) + mf * 16 + (lane >> 2);
#pragma unroll
        for (int nf = 0; nf < 4; nf++) {
            int col0 = bn + wn * 32 + nf * 8 + ((lane & 3) << 1);
            float v[4] = {acc[mf][nf][0], acc[mf][nf][1],
                          acc[mf][nf][2], acc[mf][nf][3]};
#pragma unroll
            for (int half = 0; half < 2; half++) {
                int row = rowA + half * 8;
                float v0 = v[half * 2], v1 = v[half * 2 + 1];
                if (EPI == 0) {
                    int rb = row / NUMB;
                    if (rb == (col0 + 0) / NUMB) v0 = -1000.0f;
                    if (rb == (col0 + 1) / NUMB) v1 = -1000.0f;
                    *(float2*)&Cp[(size_t)row * ldc + col0] = make_float2(v0, v1);
                } else if (EPI == 1) {
                    v0 += g_bias[z * 256 + col0];
                    v1 += g_bias[z * 256 + col0 + 1];
                    size_t o = (size_t)row * 256 + col0;
                    if (z == 0)      store_split2(g_qh, g_ql, o, v0, v1);
                    else if (z == 1) store_split2(g_kh, g_kl, o, v0, v1);
                    else             *(float2*)&g_gx[o] = make_float2(v0, v1);
                } else if (EPI == 2) {
                    *(float2*)&Cp[(size_t)row * 256 + col0] = make_float2(v0, v1);
                } else {
                    int n = row / NUMB, t = row - n * NUMB;
                    v0 += bias[col0]     + ori[(size_t)(n * 512 + col0) * NUMB + t];
                    v1 += bias[col0 + 1] + ori[(size_t)(n * 512 + col0 + 1) * NUMB + t];
                    *(float2*)&Cp[(size_t)row * ldc + col0] = make_float2(v0, v1);
                }
            }
        }
    }
}

// ---------------------------------------------------------------------------
// Row softmax in place (float4 vectorized) + emit fp16 P for the AV MMA.
// ---------------------------------------------------------------------------
__global__ void __launch_bounds__(256)
softmax_kernel(float* __restrict__ attn)
{
    const int row = blockIdx.x;
    float4* p4 = (float4*)(attn + (size_t)row * T_TOK);
    uint2*  pf4 = (uint2*)(g_pf + (size_t)row * T_TOK);
    const int tid = threadIdx.x;
    const unsigned FULL = 0xffffffffu;
    __shared__ float red[8];

    float4 v[6];
    float mx = -1e30f;
#pragma unroll
    for (int i = 0; i < 6; i++) {
        int idx = tid + (i << 8);
        if (idx < 1472) {
            v[i] = p4[idx];
            mx = fmaxf(mx, fmaxf(fmaxf(v[i].x, v[i].y), fmaxf(v[i].z, v[i].w)));
        }
    }
#pragma unroll
    for (int o = 16; o; o >>= 1) mx = fmaxf(mx, __shfl_xor_sync(FULL, mx, o));
    if ((tid & 31) == 0) red[tid >> 5] = mx;
    __syncthreads();
    if (tid < 32) {
        float m2 = (tid < 8) ? red[tid] : -1e30f;
#pragma unroll
        for (int o = 4; o; o >>= 1) m2 = fmaxf(m2, __shfl_xor_sync(FULL, m2, o));
        if (tid == 0) red[0] = m2;
    }
    __syncthreads();
    mx = red[0];
    __syncthreads();

    float s = 0.f;
#pragma unroll
    for (int i = 0; i < 6; i++) {
        int idx = tid + (i << 8);
        if (idx < 1472) {
            v[i].x = __expf(v[i].x - mx);
            v[i].y = __expf(v[i].y - mx);
            v[i].z = __expf(v[i].z - mx);
            v[i].w = __expf(v[i].w - mx);
            s += v[i].x + v[i].y + v[i].z + v[i].w;
        }
    }
#pragma unroll
    for (int o = 16; o; o >>= 1) s += __shfl_xor_sync(FULL, s, o);
    if ((tid & 31) == 0) red[tid >> 5] = s;
    __syncthreads();
    if (tid < 32) {
        float s2 = (tid < 8) ? red[tid] : 0.f;
#pragma unroll
        for (int o = 4; o; o >>= 1) s2 += __shfl_xor_sync(FULL, s2, o);
        if (tid == 0) red[0] = s2;
    }
    __syncthreads();
    float inv = 1.f / red[0];
#pragma unroll
    for (int i = 0; i < 6; i++) {
        int idx = tid + (i << 8);
        if (idx < 1472) {
            float4 r;
            r.x = v[i].x * inv; r.y = v[i].y * inv;
            r.z = v[i].z * inv; r.w = v[i].w * inv;
            p4[idx] = r;
            __half2 h0 = __floats2half2_rn(r.x, r.y);
            __half2 h1 = __floats2half2_rn(r.z, r.w);
            uint2 pk;
            pk.x = *(uint32_t*)&h0;
            pk.y = *(uint32_t*)&h1;
            pf4[idx] = pk;
        }
    }
}

// ---------------------------------------------------------------------------
extern "C" void kernel_launch(void* const* d_in, const int* in_sizes, int n_in,
                              void* d_out, int out_size)
{
    const float* ori     = (const float*)d_in[0];
    const float* gamma   = (const float*)d_in[1];
    const float* beta    = (const float*)d_in[2];
    const float* mean    = (const float*)d_in[3];
    const float* var     = (const float*)d_in[4];
    const float* theta_w = (const float*)d_in[5];
    const float* theta_b = (const float*)d_in[6];
    const float* phi_w   = (const float*)d_in[7];
    const float* phi_b   = (const float*)d_in[8];
    const float* g_w     = (const float*)d_in[9];
    const float* g_b     = (const float*)d_in[10];
    const float* W_w     = (const float*)d_in[11];
    const float* W_b     = (const float*)d_in[12];

    float* att_fea = (float*)d_out;                                  // (128,46,512)
    float* fdiv    = (float*)d_out + (size_t)NB * NUMB * 512;        // (5888,5888)

    bf16 *fh, *fl, *pwh, *pwl, *fwh, *fwl;
    bf16 *qh, *ql, *kh, *kl, *yh, *yl;
    __half *gth, *gtl, *pf;
    float *yp;
    cudaGetSymbolAddress((void**)&fh,  g_fh);
    cudaGetSymbolAddress((void**)&fl,  g_fl);
    cudaGetSymbolAddress((void**)&pwh, g_pwh);
    cudaGetSymbolAddress((void**)&pwl, g_pwl);
    cudaGetSymbolAddress((void**)&fwh, g_fwh);
    cudaGetSymbolAddress((void**)&fwl, g_fwl);
    cudaGetSymbolAddress((void**)&qh,  g_qh);
    cudaGetSymbolAddress((void**)&ql,  g_ql);
    cudaGetSymbolAddress((void**)&kh,  g_kh);
    cudaGetSymbolAddress((void**)&kl,  g_kl);
    cudaGetSymbolAddress((void**)&gth, g_gth);
    cudaGetSymbolAddress((void**)&gtl, g_gtl);
    cudaGetSymbolAddress((void**)&yh,  g_yh);
    cudaGetSymbolAddress((void**)&yl,  g_yl);
    cudaGetSymbolAddress((void**)&pf,  g_pf);
    cudaGetSymbolAddress((void**)&yp,  g_yp);

    // stage = ANUM*BM*128 + 2*16KB
    const int SM3  = 2 * (2 * 8192 + 2 * 16384) + 1024;   // 97 KB (BM=64, TERMS=3)
    const int SMAV = 2 * (1 * 8192 + 2 * 16384) + 1024;   // 81 KB (BM=64, TERMS=2)
    cudaFuncSetAttribute(hmma_gemm<64, 2, 0, 3>,
                         cudaFuncAttributeMaxDynamicSharedMemorySize, SM3);
    cudaFuncSetAttribute(hmma_gemm<64, 2, 1, 3>,
                         cudaFuncAttributeMaxDynamicSharedMemorySize, SM3);
    cudaFuncSetAttribute(hmma_gemm<64, 2, 2, 2>,
                         cudaFuncAttributeMaxDynamicSharedMemorySize, SMAV);
    cudaFuncSetAttribute(hmma_gemm<64, 2, 3, 3>,
                         cudaFuncAttributeMaxDynamicSharedMemorySize, SM3);

    // 1) BN + ReLU + transpose -> feat hi/lo (T, 512)
    bn_relu_kernel<<<dim3(16, NB), 256>>>(ori, gamma, beta, mean, var);

    // 2) Split weights / gather biases
    prep_weights<<<2048, 256>>>(theta_w, phi_w, g_w, W_w, theta_b, phi_b, g_b);

    // 3) Projections (HMMA bf16, 3-term): z=0 -> qh/ql, z=1 -> kh/kl, z=2 -> gx
    hmma_gemm<64, 2, 1, 3><<<dim3(2, 92, 3), 256, SM3>>>(
        fh, fl, pwh, pwl, nullptr, 0, 512, 512, nullptr, nullptr);

    // 4) Gt fp16 hi/lo (256, T) transpose of gx
    transpose_g_kernel<<<dim3(184, 8), 256>>>();

    // 5) attn = xt @ xp^T (HMMA bf16, 3-term) + mask -> fdiv logits
    hmma_gemm<64, 2, 0, 3><<<dim3(46, 92), 256, SM3>>>(
        qh, ql, kh, kl, fdiv, T_TOK, 256, 256, nullptr, nullptr);

    // 6) softmax rows in place; emit P fp16
    softmax_kernel<<<T_TOK, 256>>>(fdiv);

    // 7) y partials: split-K x2 (z half works on K elems [z*2944, z*2944+2944))
    hmma_gemm<64, 2, 2, 2><<<dim3(2, 92, 2), 256, SMAV>>>(
        (const bf16*)pf, nullptr, (const bf16*)gth, (const bf16*)gtl,
        yp, 256, T_TOK, 2944, nullptr, nullptr);

    // 7b) reduce partials -> y hi/lo bf16
    reduce_y_kernel<<<(T_TOK * 256 / 4) / 256, 256>>>();

    // 8) att_fea = y @ W_w^T + W_b + ori^T (HMMA bf16, 3-term)
    hmma_gemm<64, 2, 3, 3><<<dim3(4, 92), 256, SM3>>>(
        yh, yl, fwh, fwl, att_fea, 512, 256, 256, W_b, ori);
}